// round 3
// baseline (speedup 1.0000x reference)
#include <cuda_runtime.h>

// CSPN 3x3 propagation (BS=16, H=352, W=1216, f32), 8 pixels (2 float4) per thread.
// out[b,y,x] = sum_{t!=4} kernel[b,t,y,x] * input_pad[b, y+t/3-1, x+t%3-1]
//            + kernel[b,4,y,x] * input0[b,y,x]
//
// HBM-bound at compulsory traffic (~329 MB). Kernel tensor streams once ->
// __ldcs evict-first; output -> __stcs. 2x float4 per thread doubles per-thread
// MLP and gives 1KB contiguous per warp per tap for better DRAM efficiency.

#define BS 16
#define H  352
#define W  1216
#define W4 (W / 4)   // 304
#define W8 (W / 8)   // 152

__global__ __launch_bounds__(256) void cspn_kernel(
    const float4* __restrict__ ker4,    // [BS, 9, H, W4]
    const float4* __restrict__ inp4,    // [BS, H, W4]
    const float4* __restrict__ inp0_4,  // [BS, H, W4]
    float4*       __restrict__ out4)    // [BS, H, W4]
{
    int tid = blockIdx.x * blockDim.x + threadIdx.x;
    const int total = BS * H * W8;
    if (tid >= total) return;

    int x8 = tid % W8;
    int y  = (tid / W8) % H;
    int b  = tid / (W8 * H);
    int x4 = x8 * 2;             // first of the two float4s this thread owns

    const float4 z = make_float4(0.f, 0.f, 0.f, 0.f);

    // 3x10 input window: per row, 4 aligned float4 loads covering cols
    // [x0-1, x0+8]. Only lft.w and rgt.x are consumed from the edge vectors.
    float r[3][10];
#pragma unroll
    for (int dy = 0; dy < 3; dy++) {
        int yy = y + dy - 1;
        bool vy = (yy >= 0) && (yy < H);
        const float4* rp = inp4 + ((size_t)b * H + (vy ? yy : 0)) * W4;
        float4 lft = (vy && x8 > 0)      ? __ldg(rp + x4 - 1) : z;
        float4 m0  =  vy                 ? __ldg(rp + x4)     : z;
        float4 m1  =  vy                 ? __ldg(rp + x4 + 1) : z;
        float4 rgt = (vy && x8 < W8 - 1) ? __ldg(rp + x4 + 2) : z;
        r[dy][0] = lft.w;
        r[dy][1] = m0.x;  r[dy][2] = m0.y;  r[dy][3] = m0.z;  r[dy][4] = m0.w;
        r[dy][5] = m1.x;  r[dy][6] = m1.y;  r[dy][7] = m1.z;  r[dy][8] = m1.w;
        r[dy][9] = rgt.x;
    }

    const size_t ker_plane = (size_t)H * W4;
    const size_t ker_base  = (size_t)b * 9 * ker_plane + (size_t)y * W4 + x4;
    const size_t pix_base  = ((size_t)b * H + y) * W4 + x4;

    float4 acc0 = z, acc1 = z;

    // 8 neighbor taps; kernel tensor stream-once -> evict-first
#pragma unroll
    for (int t = 0; t < 9; t++) {
        if (t == 4) continue;
        float4 k0 = __ldcs(&ker4[ker_base + (size_t)t * ker_plane]);
        float4 k1 = __ldcs(&ker4[ker_base + (size_t)t * ker_plane + 1]);
        int dy = t / 3;
        int dx = t % 3;
        acc0.x = fmaf(k0.x, r[dy][dx + 0], acc0.x);
        acc0.y = fmaf(k0.y, r[dy][dx + 1], acc0.y);
        acc0.z = fmaf(k0.z, r[dy][dx + 2], acc0.z);
        acc0.w = fmaf(k0.w, r[dy][dx + 3], acc0.w);
        acc1.x = fmaf(k1.x, r[dy][dx + 4], acc1.x);
        acc1.y = fmaf(k1.y, r[dy][dx + 5], acc1.y);
        acc1.z = fmaf(k1.z, r[dy][dx + 6], acc1.z);
        acc1.w = fmaf(k1.w, r[dy][dx + 7], acc1.w);
    }

    // Center tap: input0 replaces the im2col center
    {
        float4 k0 = __ldcs(&ker4[ker_base + (size_t)4 * ker_plane]);
        float4 k1 = __ldcs(&ker4[ker_base + (size_t)4 * ker_plane + 1]);
        float4 c0 = __ldg(&inp0_4[pix_base]);
        float4 c1 = __ldg(&inp0_4[pix_base + 1]);
        acc0.x = fmaf(k0.x, c0.x, acc0.x);
        acc0.y = fmaf(k0.y, c0.y, acc0.y);
        acc0.z = fmaf(k0.z, c0.z, acc0.z);
        acc0.w = fmaf(k0.w, c0.w, acc0.w);
        acc1.x = fmaf(k1.x, c1.x, acc1.x);
        acc1.y = fmaf(k1.y, c1.y, acc1.y);
        acc1.z = fmaf(k1.z, c1.z, acc1.z);
        acc1.w = fmaf(k1.w, c1.w, acc1.w);
    }

    __stcs(&out4[pix_base],     acc0);
    __stcs(&out4[pix_base + 1], acc1);
}

extern "C" void kernel_launch(void* const* d_in, const int* in_sizes, int n_in,
                              void* d_out, int out_size)
{
    const float4* ker4   = (const float4*)d_in[0];
    const float4* inp4   = (const float4*)d_in[1];
    const float4* inp0_4 = (const float4*)d_in[2];
    float4*       out4   = (float4*)d_out;

    const int total   = BS * H * W8;        // 856,064 threads
    const int threads = 256;
    const int blocks  = (total + threads - 1) / threads;
    cspn_kernel<<<blocks, threads>>>(ker4, inp4, inp0_4, out4);
}

// round 4
// speedup vs baseline: 1.0503x; 1.0503x over previous
#include <cuda_runtime.h>

// CSPN 3x3 propagation (BS=16, H=352, W=1216, f32), 1 float4 per thread.
// Row-wise structure + 32-reg cap (launch_bounds 256,8) for full occupancy.
// Only tap t=4 (center) uses input0; all other taps use zero-padded input.

#define BS 16
#define H  352
#define W  1216
#define W4 (W / 4)   // 304

__global__ __launch_bounds__(256, 8) void cspn_kernel(
    const float4* __restrict__ ker4,    // [BS, 9, H, W4]
    const float4* __restrict__ inp4,    // [BS, H, W4]
    const float4* __restrict__ inp0_4,  // [BS, H, W4]
    float4*       __restrict__ out4)    // [BS, H, W4]
{
    int tid = blockIdx.x * blockDim.x + threadIdx.x;
    const int total = BS * H * W4;
    if (tid >= total) return;

    int x4 = tid % W4;
    int y  = (tid / W4) % H;
    int b  = tid / (W4 * H);

    const float4 z = make_float4(0.f, 0.f, 0.f, 0.f);

    const size_t ker_plane = (size_t)H * W4;
    const size_t ker_base  = (size_t)b * 9 * ker_plane + (size_t)y * W4 + x4;
    const size_t pix_base  = ((size_t)b * H + y) * W4 + x4;

    bool has_l = (x4 > 0);
    bool has_r = (x4 < W4 - 1);

    float4 acc = z;

#pragma unroll
    for (int dy = 0; dy < 3; dy++) {
        int yy = y + dy - 1;
        bool vy = (yy >= 0) && (yy < H);
        const float4* rp = inp4 + ((size_t)b * H + (vy ? yy : 0)) * W4;

        float4 lft = (vy && has_l) ? __ldg(rp + x4 - 1) : z;
        float4 mid =  vy           ? __ldg(rp + x4)     : z;
        float4 rgt = (vy && has_r) ? __ldg(rp + x4 + 1) : z;

        float4 k0 = __ldcs(&ker4[ker_base + (size_t)(dy * 3 + 0) * ker_plane]);
        float4 k1 = __ldcs(&ker4[ker_base + (size_t)(dy * 3 + 1) * ker_plane]);
        float4 k2 = __ldcs(&ker4[ker_base + (size_t)(dy * 3 + 2) * ker_plane]);

        // center tap (t=4): kernel * input0 instead of kernel * input
        float4 c = (dy == 1) ? __ldg(&inp0_4[pix_base]) : mid;

        // tap dx=0: cols x0-1..x0+2
        acc.x = fmaf(k0.x, lft.w, acc.x);
        acc.y = fmaf(k0.y, mid.x, acc.y);
        acc.z = fmaf(k0.z, mid.y, acc.z);
        acc.w = fmaf(k0.w, mid.z, acc.w);
        // tap dx=1 (center column): dy==1 -> input0, else input
        acc.x = fmaf(k1.x, c.x, acc.x);
        acc.y = fmaf(k1.y, c.y, acc.y);
        acc.z = fmaf(k1.z, c.z, acc.z);
        acc.w = fmaf(k1.w, c.w, acc.w);
        // tap dx=2: cols x0+1..x0+4
        acc.x = fmaf(k2.x, mid.y, acc.x);
        acc.y = fmaf(k2.y, mid.z, acc.y);
        acc.z = fmaf(k2.z, mid.w, acc.z);
        acc.w = fmaf(k2.w, rgt.x, acc.w);
    }

    __stcs(&out4[pix_base], acc);
}

extern "C" void kernel_launch(void* const* d_in, const int* in_sizes, int n_in,
                              void* d_out, int out_size)
{
    const float4* ker4   = (const float4*)d_in[0];
    const float4* inp4   = (const float4*)d_in[1];
    const float4* inp0_4 = (const float4*)d_in[2];
    float4*       out4   = (float4*)d_out;

    const int total   = BS * H * W4;
    const int threads = 256;
    const int blocks  = (total + threads - 1) / threads;
    cspn_kernel<<<blocks, threads>>>(ker4, inp4, inp0_4, out4);
}

// round 5
// speedup vs baseline: 1.1059x; 1.0529x over previous
#include <cuda_runtime.h>

// CSPN 3x3 propagation (BS=16, H=352, W=1216, f32), persistent grid-stride.
// Grid = 148 SMs x 8 resident blocks = 1184 blocks; each thread processes
// ~5.65 float4 pixels. Removes the partial-final-wave imbalance of the
// 6688-block launch. Body identical to R4 (32 regs, full occupancy).
// Kernel tensor streams once -> __ldcs; output -> __stcs.

#define BS 16
#define H  352
#define W  1216
#define W4 (W / 4)   // 304

#define NSM    148
#define BLKSM  8
#define NBLK   (NSM * BLKSM)   // 1184

__global__ __launch_bounds__(256, 8) void cspn_kernel(
    const float4* __restrict__ ker4,    // [BS, 9, H, W4]
    const float4* __restrict__ inp4,    // [BS, H, W4]
    const float4* __restrict__ inp0_4,  // [BS, H, W4]
    float4*       __restrict__ out4)    // [BS, H, W4]
{
    const unsigned total  = BS * H * W4;            // 1,712,128
    const unsigned stride = gridDim.x * blockDim.x; // 303,104

    const float4 z = make_float4(0.f, 0.f, 0.f, 0.f);
    const size_t ker_plane = (size_t)H * W4;

    for (unsigned tid = blockIdx.x * blockDim.x + threadIdx.x;
         tid < total; tid += stride)
    {
        unsigned x4 = tid % W4;
        unsigned y  = (tid / W4) % H;
        unsigned b  = tid / (W4 * H);

        const size_t ker_base = (size_t)b * 9 * ker_plane + (size_t)y * W4 + x4;
        const size_t pix_base = ((size_t)b * H + y) * W4 + x4;

        bool has_l = (x4 > 0);
        bool has_r = (x4 < W4 - 1);

        float4 acc = z;

#pragma unroll
        for (int dy = 0; dy < 3; dy++) {
            int yy = (int)y + dy - 1;
            bool vy = (yy >= 0) && (yy < H);
            const float4* rp = inp4 + ((size_t)b * H + (vy ? yy : 0)) * W4;

            float4 lft = (vy && has_l) ? __ldg(rp + x4 - 1) : z;
            float4 mid =  vy           ? __ldg(rp + x4)     : z;
            float4 rgt = (vy && has_r) ? __ldg(rp + x4 + 1) : z;

            float4 k0 = __ldcs(&ker4[ker_base + (size_t)(dy * 3 + 0) * ker_plane]);
            float4 k1 = __ldcs(&ker4[ker_base + (size_t)(dy * 3 + 1) * ker_plane]);
            float4 k2 = __ldcs(&ker4[ker_base + (size_t)(dy * 3 + 2) * ker_plane]);

            // center tap (t=4): kernel * input0 instead of kernel * input
            float4 c = (dy == 1) ? __ldg(&inp0_4[pix_base]) : mid;

            // tap dx=0: cols x0-1..x0+2
            acc.x = fmaf(k0.x, lft.w, acc.x);
            acc.y = fmaf(k0.y, mid.x, acc.y);
            acc.z = fmaf(k0.z, mid.y, acc.z);
            acc.w = fmaf(k0.w, mid.z, acc.w);
            // tap dx=1 (center column): dy==1 -> input0, else input
            acc.x = fmaf(k1.x, c.x, acc.x);
            acc.y = fmaf(k1.y, c.y, acc.y);
            acc.z = fmaf(k1.z, c.z, acc.z);
            acc.w = fmaf(k1.w, c.w, acc.w);
            // tap dx=2: cols x0+1..x0+4
            acc.x = fmaf(k2.x, mid.y, acc.x);
            acc.y = fmaf(k2.y, mid.z, acc.y);
            acc.z = fmaf(k2.z, mid.w, acc.z);
            acc.w = fmaf(k2.w, rgt.x, acc.w);
        }

        __stcs(&out4[pix_base], acc);
    }
}

extern "C" void kernel_launch(void* const* d_in, const int* in_sizes, int n_in,
                              void* d_out, int out_size)
{
    const float4* ker4   = (const float4*)d_in[0];
    const float4* inp4   = (const float4*)d_in[1];
    const float4* inp0_4 = (const float4*)d_in[2];
    float4*       out4   = (float4*)d_out;

    cspn_kernel<<<NBLK, 256>>>(ker4, inp4, inp0_4, out4);
}